// round 7
// baseline (speedup 1.0000x reference)
#include <cuda_runtime.h>
#include <cuda_bf16.h>
#include <math.h>
#include <stdint.h>

// Problem constants
#define BSZ 2
#define SEQ 2048
#define DIM 4096
#define NH 32
#define NKV 8
#define HD 128
#define TOKENS (BSZ*SEQ)   // 4096
#define K3 12288           // 3 * DIM (hi|hi|lo concat)

// ---------------------------------------------------------------------------
// Scratch (device globals — no allocation allowed)
// ---------------------------------------------------------------------------
__device__ float g_xq[(size_t)TOKENS * NH * HD];    // 4096 x 4096
__device__ float g_xk[(size_t)TOKENS * NKV * HD];   // 4096 x 1024
__device__ float g_xv[(size_t)TOKENS * NKV * HD];   // 4096 x 1024
__device__ float g_attn[(size_t)TOKENS * NH * HD];  // 4096 x 4096

__device__ __nv_bfloat16 g_x3  [(size_t)TOKENS * K3];  // x split    [4096,12288]
__device__ __nv_bfloat16 g_at3 [(size_t)TOKENS * K3];  // attn split
__device__ __nv_bfloat16 g_wq3 [(size_t)4096 * K3];    // wq^T split [N,K3]
__device__ __nv_bfloat16 g_wk3 [(size_t)1024 * K3];
__device__ __nv_bfloat16 g_wv3 [(size_t)1024 * K3];
__device__ __nv_bfloat16 g_wo3 [(size_t)4096 * K3];

// ---------------------------------------------------------------------------
// PTX helpers (sm_80+ portable: cp.async / ldmatrix / mma.sync)
// ---------------------------------------------------------------------------
__device__ __forceinline__ uint32_t smem_u32(const void* p) {
    uint32_t a;
    asm("{ .reg .u64 t; cvta.to.shared.u64 t, %1; cvt.u32.u64 %0, t; }" : "=r"(a) : "l"(p));
    return a;
}
__device__ __forceinline__ void cp16(uint32_t s, const void* g) {
    asm volatile("cp.async.cg.shared.global [%0], [%1], 16;" :: "r"(s), "l"(g) : "memory");
}
__device__ __forceinline__ void cp_commit() {
    asm volatile("cp.async.commit_group;" ::: "memory");
}
template<int N> __device__ __forceinline__ void cp_wait() {
    asm volatile("cp.async.wait_group %0;" :: "n"(N) : "memory");
}
__device__ __forceinline__ void ldm_x4(uint32_t* r, uint32_t addr) {
    asm volatile("ldmatrix.sync.aligned.m8n8.x4.shared.b16 {%0,%1,%2,%3}, [%4];"
                 : "=r"(r[0]), "=r"(r[1]), "=r"(r[2]), "=r"(r[3]) : "r"(addr));
}
__device__ __forceinline__ void mma_bf16(float* d, const uint32_t* a, const uint32_t* b) {
    asm volatile(
        "mma.sync.aligned.m16n8k16.row.col.f32.bf16.bf16.f32 "
        "{%0,%1,%2,%3}, {%4,%5,%6,%7}, {%8,%9}, {%0,%1,%2,%3};"
        : "+f"(d[0]), "+f"(d[1]), "+f"(d[2]), "+f"(d[3])
        : "r"(a[0]), "r"(a[1]), "r"(a[2]), "r"(a[3]), "r"(b[0]), "r"(b[1]));
}

// ---------------------------------------------------------------------------
// Split/convert kernels
// ---------------------------------------------------------------------------
// Activation split: A[M,4096] f32 -> A3[M,12288] bf16 = [hi | hi | lo]
__global__ void split_act_kernel(const float* __restrict__ A,
                                 __nv_bfloat16* __restrict__ A3, int total)
{
    int i = blockIdx.x * blockDim.x + threadIdx.x;
    if (i >= total) return;
    int m = i >> 12;          // /4096
    int k = i & 4095;
    float v = A[i];
    __nv_bfloat16 hi = __float2bfloat16(v);
    __nv_bfloat16 lo = __float2bfloat16(v - __bfloat162float(hi));
    size_t base = (size_t)m * K3;
    A3[base + k]        = hi;
    A3[base + 4096 + k] = hi;
    A3[base + 8192 + k] = lo;
}

// Weight transpose+split: W[4096,N] f32 -> W3[N,12288] bf16 = [hi | lo | hi]
__global__ void transpose_split_kernel(const float* __restrict__ W,
                                       __nv_bfloat16* __restrict__ W3, int N)
{
    __shared__ float t[32][33];
    int k0 = blockIdx.x * 32, n0 = blockIdx.y * 32;
    int tx = threadIdx.x, ty = threadIdx.y;   // 32 x 8
    #pragma unroll
    for (int j = 0; j < 4; j++)
        t[ty + j * 8][tx] = W[(size_t)(k0 + ty + j * 8) * N + n0 + tx];
    __syncthreads();
    #pragma unroll
    for (int j = 0; j < 4; j++) {
        int n = n0 + ty + j * 8;
        int k = k0 + tx;
        float v = t[tx][ty + j * 8];
        __nv_bfloat16 hi = __float2bfloat16(v);
        __nv_bfloat16 lo = __float2bfloat16(v - __bfloat162float(hi));
        size_t base = (size_t)n * K3;
        W3[base + k]        = hi;
        W3[base + 4096 + k] = lo;
        W3[base + 8192 + k] = hi;
    }
}

// ---------------------------------------------------------------------------
// HMMA GEMM: C[M,N] = A3[M,K3] . B3[N,K3]^T   (bf16 in, fp32 out)
// BM=BN=128, BK=64, 256 threads (8 warps, warp tile 32x64).
// 3-stage cp.async ring, ONE __syncthreads per chunk.
// Smem row = 64 bf16 = 128B; chunk swizzle c ^ (row&7) -> conflict-free ldmatrix.
// ---------------------------------------------------------------------------
#define STAGES 3
#define STAGE_BYTES 32768
#define HG_SMEM (STAGES * STAGE_BYTES)   // 96 KB -> 2 CTAs/SM
#define NKC (K3 / 64)   // 192

__global__ __launch_bounds__(256) void hgemm_kernel(
    const __nv_bfloat16* __restrict__ A3,
    const __nv_bfloat16* __restrict__ B3,
    float* __restrict__ C, int N)
{
    extern __shared__ char smraw[];
    const uint32_t sbase = smem_u32(smraw);   // per stage: A(16KB) | B(16KB)

    const int tid  = threadIdx.x;
    const int lane = tid & 31, warp = tid >> 5;
    const int wm = warp & 3;      // m offset wm*32
    const int wn = warp >> 2;     // n offset wn*64
    const int m0 = blockIdx.y * 128;
    const int n0 = blockIdx.x * 128;

    // loader: each thread owns rows lrow+32i at 16B-chunk lc
    const int lrow = tid >> 3;    // 0..31
    const int lc   = tid & 7;     // 0..7
    const __nv_bfloat16* gA = A3 + (size_t)(m0 + lrow) * K3 + lc * 8;
    const __nv_bfloat16* gB = B3 + (size_t)(n0 + lrow) * K3 + lc * 8;
    uint32_t soff[4];
    #pragma unroll
    for (int i = 0; i < 4; i++) {
        int row = lrow + 32 * i;
        soff[i] = row * 128 + ((lc ^ (row & 7)) * 16);
    }

    auto load_chunk = [&](int buf, int kc) {
        uint32_t sA = sbase + buf * STAGE_BYTES;
        uint32_t sB = sA + 16384;
        size_t koff = (size_t)kc * 64;
        #pragma unroll
        for (int i = 0; i < 4; i++) {
            cp16(sA + soff[i], gA + (size_t)(32 * i) * K3 + koff);
            cp16(sB + soff[i], gB + (size_t)(32 * i) * K3 + koff);
        }
    };

    float d[2][8][4];
    #pragma unroll
    for (int mi = 0; mi < 2; mi++)
        #pragma unroll
        for (int ni = 0; ni < 8; ni++)
            #pragma unroll
            for (int j = 0; j < 4; j++) d[mi][ni][j] = 0.f;

    // prologue: fill STAGES-1 stages
    load_chunk(0, 0); cp_commit();
    load_chunk(1, 1); cp_commit();

    // precomputed ldmatrix row/col pieces
    const int aRow0 = wm * 32 + (lane & 15);
    const int aSel  = lane >> 4;
    const int bRow0 = wn * 64 + ((lane >> 4) & 1) * 8 + (lane & 7);
    const int bSel  = (lane >> 3) & 1;

    int buf = 0;
    for (int kc = 0; kc < NKC; kc++) {
        cp_wait<STAGES - 2>();
        __syncthreads();

        // issue loads for stage kc+2 (overwrites buffer finished at last sync)
        if (kc + 2 < NKC) {
            int nb = buf + 2; if (nb >= STAGES) nb -= STAGES;
            load_chunk(nb, kc + 2);
        }
        cp_commit();

        uint32_t sA = sbase + buf * STAGE_BYTES;
        uint32_t sB = sA + 16384;

        #pragma unroll
        for (int ks = 0; ks < 4; ks++) {
            uint32_t aF[2][4];
            #pragma unroll
            for (int mi = 0; mi < 2; mi++) {
                int row = aRow0 + mi * 16;
                uint32_t c = (uint32_t)((ks * 2 + aSel) ^ (row & 7));
                ldm_x4(aF[mi], sA + row * 128 + c * 16);
            }
            uint32_t bF[8][2];
            #pragma unroll
            for (int p = 0; p < 4; p++) {
                int row = bRow0 + p * 16;
                uint32_t c = (uint32_t)((ks * 2 + bSel) ^ (row & 7));
                uint32_t r[4];
                ldm_x4(r, sB + row * 128 + c * 16);
                bF[2*p][0] = r[0]; bF[2*p][1] = r[1];
                bF[2*p+1][0] = r[2]; bF[2*p+1][1] = r[3];
            }
            #pragma unroll
            for (int mi = 0; mi < 2; mi++)
                #pragma unroll
                for (int ni = 0; ni < 8; ni++)
                    mma_bf16(d[mi][ni], aF[mi], bF[ni]);
        }

        buf++; if (buf >= STAGES) buf = 0;
    }

    // epilogue
    #pragma unroll
    for (int mi = 0; mi < 2; mi++) {
        int r0 = m0 + wm * 32 + mi * 16 + (lane >> 2);
        #pragma unroll
        for (int ni = 0; ni < 8; ni++) {
            int col = n0 + wn * 64 + ni * 8 + (lane & 3) * 2;
            *(float2*)&C[(size_t)r0 * N + col]       = make_float2(d[mi][ni][0], d[mi][ni][1]);
            *(float2*)&C[(size_t)(r0 + 8) * N + col] = make_float2(d[mi][ni][2], d[mi][ni][3]);
        }
    }
}

// ---------------------------------------------------------------------------
// RoPE: in-place on [TOKENS, H, 128] tensor.
// ---------------------------------------------------------------------------
__global__ void rope_kernel(float* __restrict__ t,
                            const float* __restrict__ fc,
                            const float* __restrict__ fs, int H, int total)
{
    int i = blockIdx.x * blockDim.x + threadIdx.x;
    if (i >= total) return;
    int half = i & 63;
    int h    = (i >> 6) % H;
    int tok  = i / (64 * H);
    int s    = tok & (SEQ - 1);
    float c  = fc[s * 64 + half];
    float sn = fs[s * 64 + half];
    float* p = t + (((size_t)tok * H + h) * HD) + 2 * half;
    float a = p[0], b = p[1];
    p[0] = a * c - b * sn;
    p[1] = a * sn + b * c;
}

// ---------------------------------------------------------------------------
// Causal flash attention, fp32, GQA (unchanged — passed in R1/R6)
// ---------------------------------------------------------------------------
__global__ __launch_bounds__(256) void flash_kernel(
    const float* __restrict__ q, const float* __restrict__ k,
    const float* __restrict__ v, float* __restrict__ o)
{
    constexpr int BM = 64, BN = 32, D = HD;
    __shared__ float Ks[BN][D];
    __shared__ float Vs[BN][D];

    const int m0 = blockIdx.x * BM;
    const int h  = blockIdx.y;
    const int b  = blockIdx.z;
    const int kh = h >> 2;
    const int tid = threadIdx.x;
    const int row = tid >> 2;
    const int c4  = tid & 3;
    const int qrow = m0 + row;

    float qreg[32];
    {
        const float* qp = q + (((size_t)b * SEQ + qrow) * NH + h) * D + c4 * 32;
        #pragma unroll
        for (int d = 0; d < 32; d += 4) {
            float4 t = *(const float4*)(qp + d);
            qreg[d] = t.x; qreg[d+1] = t.y; qreg[d+2] = t.z; qreg[d+3] = t.w;
        }
    }

    float acc[32];
    #pragma unroll
    for (int d = 0; d < 32; d++) acc[d] = 0.f;
    float m = -INFINITY, l = 0.f;
    const float scale = 0.08838834764831845f;

    for (int j0 = 0; j0 < m0 + BM; j0 += BN) {
        {
            int base = tid * 16;
            int tr = base >> 7, tc = base & 127;
            const float* kp = k + (((size_t)b * SEQ + j0 + tr) * NKV + kh) * D + tc;
            const float* vp = v + (((size_t)b * SEQ + j0 + tr) * NKV + kh) * D + tc;
            #pragma unroll
            for (int u = 0; u < 16; u += 4) {
                *(float4*)&Ks[tr][tc + u] = *(const float4*)(kp + u);
                *(float4*)&Vs[tr][tc + u] = *(const float4*)(vp + u);
            }
        }
        __syncthreads();

        float s[BN];
        float tile_max = -INFINITY;
        #pragma unroll
        for (int j = 0; j < BN; j++) {
            float p = 0.f;
            const float4* kr = (const float4*)&Ks[j][c4 * 32];
            #pragma unroll
            for (int d4 = 0; d4 < 8; d4++) {
                float4 kv = kr[d4];
                p += qreg[4*d4+0]*kv.x + qreg[4*d4+1]*kv.y
                   + qreg[4*d4+2]*kv.z + qreg[4*d4+3]*kv.w;
            }
            p += __shfl_xor_sync(0xffffffffu, p, 1);
            p += __shfl_xor_sync(0xffffffffu, p, 2);
            p *= scale;
            if (j0 + j > qrow) p = -INFINITY;
            s[j] = p;
            tile_max = fmaxf(tile_max, p);
        }

        float m_new = fmaxf(m, tile_max);
        float corr = __expf(m - m_new);
        l *= corr;
        #pragma unroll
        for (int d = 0; d < 32; d++) acc[d] *= corr;

        #pragma unroll
        for (int j = 0; j < BN; j++) {
            float p = __expf(s[j] - m_new);
            l += p;
            const float4* vr = (const float4*)&Vs[j][c4 * 32];
            #pragma unroll
            for (int d4 = 0; d4 < 8; d4++) {
                float4 vv = vr[d4];
                acc[4*d4+0] += p * vv.x;
                acc[4*d4+1] += p * vv.y;
                acc[4*d4+2] += p * vv.z;
                acc[4*d4+3] += p * vv.w;
            }
        }
        m = m_new;
        __syncthreads();
    }

    float inv = 1.f / l;
    float* op = o + (((size_t)b * SEQ + qrow) * NH + h) * D + c4 * 32;
    #pragma unroll
    for (int d = 0; d < 32; d += 4) {
        float4 t = make_float4(acc[d]*inv, acc[d+1]*inv, acc[d+2]*inv, acc[d+3]*inv);
        *(float4*)(op + d) = t;
    }
}

// ---------------------------------------------------------------------------
extern "C" void kernel_launch(void* const* d_in, const int* in_sizes, int n_in,
                              void* d_out, int out_size)
{
    const float* x  = (const float*)d_in[0];
    const float* wq = (const float*)d_in[1];
    const float* wk = (const float*)d_in[2];
    const float* wv = (const float*)d_in[3];
    const float* wo = (const float*)d_in[4];
    const float* fc = (const float*)d_in[7];
    const float* fs = (const float*)d_in[8];
    float* out = (float*)d_out;

    float *xq, *xk, *xv, *attn;
    __nv_bfloat16 *x3, *at3, *wq3, *wk3, *wv3, *wo3;
    cudaGetSymbolAddress((void**)&xq,   g_xq);
    cudaGetSymbolAddress((void**)&xk,   g_xk);
    cudaGetSymbolAddress((void**)&xv,   g_xv);
    cudaGetSymbolAddress((void**)&attn, g_attn);
    cudaGetSymbolAddress((void**)&x3,   g_x3);
    cudaGetSymbolAddress((void**)&at3,  g_at3);
    cudaGetSymbolAddress((void**)&wq3,  g_wq3);
    cudaGetSymbolAddress((void**)&wk3,  g_wk3);
    cudaGetSymbolAddress((void**)&wv3,  g_wv3);
    cudaGetSymbolAddress((void**)&wo3,  g_wo3);

    cudaFuncSetAttribute(hgemm_kernel, cudaFuncAttributeMaxDynamicSharedMemorySize,
                         HG_SMEM);

    // Splits / transposes
    {
        int total = TOKENS * DIM;
        split_act_kernel<<<(total + 255) / 256, 256>>>(x, x3, total);
        dim3 blk(32, 8);
        transpose_split_kernel<<<dim3(128, 128), blk>>>(wq, wq3, 4096);
        transpose_split_kernel<<<dim3(128,  32), blk>>>(wk, wk3, 1024);
        transpose_split_kernel<<<dim3(128,  32), blk>>>(wv, wv3, 1024);
        transpose_split_kernel<<<dim3(128, 128), blk>>>(wo, wo3, 4096);
    }

    // QKV projections (HMMA)
    hgemm_kernel<<<dim3(4096/128, TOKENS/128), 256, HG_SMEM>>>(x3, wq3, xq, 4096);
    hgemm_kernel<<<dim3(1024/128, TOKENS/128), 256, HG_SMEM>>>(x3, wk3, xk, 1024);
    hgemm_kernel<<<dim3(1024/128, TOKENS/128), 256, HG_SMEM>>>(x3, wv3, xv, 1024);

    // RoPE
    {
        int tq = TOKENS * NH * 64;
        rope_kernel<<<(tq + 255) / 256, 256>>>(xq, fc, fs, NH, tq);
        int tk = TOKENS * NKV * 64;
        rope_kernel<<<(tk + 255) / 256, 256>>>(xk, fc, fs, NKV, tk);
    }

    // Causal flash attention (start_pos = 0, cache zero => keys/values = xk/xv)
    {
        dim3 g(SEQ / 64, NH, BSZ);
        flash_kernel<<<g, 256>>>(xq, xk, xv, attn);
    }

    // Output projection (HMMA)
    {
        int total = TOKENS * DIM;
        split_act_kernel<<<(total + 255) / 256, 256>>>(attn, at3, total);
        hgemm_kernel<<<dim3(4096/128, TOKENS/128), 256, HG_SMEM>>>(at3, wo3, out, 4096);
    }
}

// round 11
// speedup vs baseline: 1.5578x; 1.5578x over previous
#include <cuda_runtime.h>
#include <cuda_bf16.h>
#include <math.h>
#include <stdint.h>

// Problem constants
#define BSZ 2
#define SEQ 2048
#define DIM 4096
#define NH 32
#define NKV 8
#define HD 128
#define TOKENS (BSZ*SEQ)   // 4096

// ---------------------------------------------------------------------------
// Scratch (device globals — no allocation allowed)
// ---------------------------------------------------------------------------
__device__ float g_xq[(size_t)TOKENS * NH * HD];    // 4096 x 4096
__device__ float g_xk[(size_t)TOKENS * NKV * HD];   // 4096 x 1024
__device__ float g_xv[(size_t)TOKENS * NKV * HD];   // 4096 x 1024
__device__ float g_attn[(size_t)TOKENS * NH * HD];  // 4096 x 4096

__device__ __nv_bfloat16 g_xhi [(size_t)TOKENS * DIM];
__device__ __nv_bfloat16 g_xlo [(size_t)TOKENS * DIM];
__device__ __nv_bfloat16 g_athi[(size_t)TOKENS * DIM];
__device__ __nv_bfloat16 g_atlo[(size_t)TOKENS * DIM];
__device__ __nv_bfloat16 g_wqhi[(size_t)4096 * DIM];  // [N,K] transposed
__device__ __nv_bfloat16 g_wqlo[(size_t)4096 * DIM];
__device__ __nv_bfloat16 g_wkhi[(size_t)1024 * DIM];
__device__ __nv_bfloat16 g_wklo[(size_t)1024 * DIM];
__device__ __nv_bfloat16 g_wvhi[(size_t)1024 * DIM];
__device__ __nv_bfloat16 g_wvlo[(size_t)1024 * DIM];
__device__ __nv_bfloat16 g_wohi[(size_t)4096 * DIM];
__device__ __nv_bfloat16 g_wolo[(size_t)4096 * DIM];

// ---------------------------------------------------------------------------
// PTX helpers (sm_80+ portable: cp.async / ldmatrix / mma.sync)
// ---------------------------------------------------------------------------
__device__ __forceinline__ uint32_t smem_u32(const void* p) {
    uint32_t a;
    asm("{ .reg .u64 t; cvta.to.shared.u64 t, %1; cvt.u32.u64 %0, t; }" : "=r"(a) : "l"(p));
    return a;
}
__device__ __forceinline__ void cp16(uint32_t s, const void* g) {
    asm volatile("cp.async.cg.shared.global [%0], [%1], 16;" :: "r"(s), "l"(g) : "memory");
}
__device__ __forceinline__ void cp_commit() {
    asm volatile("cp.async.commit_group;" ::: "memory");
}
template<int N> __device__ __forceinline__ void cp_wait() {
    asm volatile("cp.async.wait_group %0;" :: "n"(N) : "memory");
}
__device__ __forceinline__ void ldm_x4(uint32_t* r, uint32_t addr) {
    asm volatile("ldmatrix.sync.aligned.m8n8.x4.shared.b16 {%0,%1,%2,%3}, [%4];"
                 : "=r"(r[0]), "=r"(r[1]), "=r"(r[2]), "=r"(r[3]) : "r"(addr));
}
__device__ __forceinline__ void mma_bf16(float* d, const uint32_t* a, const uint32_t* b) {
    asm volatile(
        "mma.sync.aligned.m16n8k16.row.col.f32.bf16.bf16.f32 "
        "{%0,%1,%2,%3}, {%4,%5,%6,%7}, {%8,%9}, {%0,%1,%2,%3};"
        : "+f"(d[0]), "+f"(d[1]), "+f"(d[2]), "+f"(d[3])
        : "r"(a[0]), "r"(a[1]), "r"(a[2]), "r"(a[3]), "r"(b[0]), "r"(b[1]));
}

// ---------------------------------------------------------------------------
// Split/convert kernels (hi/lo pair, no K inflation)
// ---------------------------------------------------------------------------
__global__ void split_act_kernel(const float* __restrict__ A,
                                 __nv_bfloat16* __restrict__ Ahi,
                                 __nv_bfloat16* __restrict__ Alo, int total)
{
    int i = blockIdx.x * blockDim.x + threadIdx.x;
    if (i >= total) return;
    float v = A[i];
    __nv_bfloat16 hi = __float2bfloat16(v);
    __nv_bfloat16 lo = __float2bfloat16(v - __bfloat162float(hi));
    Ahi[i] = hi;
    Alo[i] = lo;
}

// Weight transpose+split: W[4096,N] f32 -> Whi/Wlo [N,4096] bf16
__global__ void transpose_split_kernel(const float* __restrict__ W,
                                       __nv_bfloat16* __restrict__ Whi,
                                       __nv_bfloat16* __restrict__ Wlo, int N)
{
    __shared__ float t[32][33];
    int k0 = blockIdx.x * 32, n0 = blockIdx.y * 32;
    int tx = threadIdx.x, ty = threadIdx.y;   // 32 x 8
    #pragma unroll
    for (int j = 0; j < 4; j++)
        t[ty + j * 8][tx] = W[(size_t)(k0 + ty + j * 8) * N + n0 + tx];
    __syncthreads();
    #pragma unroll
    for (int j = 0; j < 4; j++) {
        int n = n0 + ty + j * 8;
        int k = k0 + tx;
        float v = t[tx][ty + j * 8];
        __nv_bfloat16 hi = __float2bfloat16(v);
        __nv_bfloat16 lo = __float2bfloat16(v - __bfloat162float(hi));
        size_t idx = (size_t)n * DIM + k;
        Whi[idx] = hi;
        Wlo[idx] = lo;
    }
}

// ---------------------------------------------------------------------------
// Fused hi/lo HMMA GEMM: C = (Ahi+Alo)(Bhi+Blo)^T - Alo·Blo  (3 products)
// K = 4096, BM=BN=128, BK=32, 256 threads (8 warps, warp tile 32x64).
// Stage holds 4 tiles: Ahi|Alo|Bhi|Blo, 8KB each (128 rows x 64B, swizzled).
// 2-stage cp.async pipeline (R6-proven ordering).
// ---------------------------------------------------------------------------
#define STAGE_BYTES 32768
#define HG_SMEM (2 * STAGE_BYTES)   // 64 KB
#define NKC (DIM / 32)              // 128

__global__ __launch_bounds__(256) void hgemm_kernel(
    const __nv_bfloat16* __restrict__ Ahi, const __nv_bfloat16* __restrict__ Alo,
    const __nv_bfloat16* __restrict__ Bhi, const __nv_bfloat16* __restrict__ Blo,
    float* __restrict__ C, int N)
{
    extern __shared__ char smraw[];
    const uint32_t sbase = smem_u32(smraw);

    const int tid  = threadIdx.x;
    const int lane = tid & 31, warp = tid >> 5;
    const int wm = warp & 3;      // m offset wm*32
    const int wn = warp >> 2;     // n offset wn*64
    const int m0 = blockIdx.y * 128;
    const int n0 = blockIdx.x * 128;

    // loader: thread t -> row t>>1 (0..127), chunk pair (t&1)*2 .. +1 (16B chunks)
    const int lrow = tid >> 1;
    const int lc0  = (tid & 1) * 2;
    const size_t arow = (size_t)(m0 + lrow) * DIM;
    const size_t brow = (size_t)(n0 + lrow) * DIM;
    uint32_t so[2];
    #pragma unroll
    for (int c = 0; c < 2; c++)
        so[c] = lrow * 64 + (((lc0 + c) ^ ((lrow >> 1) & 3)) * 16);

    auto load_chunk = [&](int buf, int kc) {
        uint32_t st = sbase + buf * STAGE_BYTES;
        size_t g = kc * 32 + lc0 * 8;
        #pragma unroll
        for (int c = 0; c < 2; c++) {
            cp16(st +         so[c], Ahi + arow + g + c * 8);
            cp16(st +  8192 + so[c], Alo + arow + g + c * 8);
            cp16(st + 16384 + so[c], Bhi + brow + g + c * 8);
            cp16(st + 24576 + so[c], Blo + brow + g + c * 8);
        }
    };

    float d[2][8][4];
    #pragma unroll
    for (int mi = 0; mi < 2; mi++)
        #pragma unroll
        for (int ni = 0; ni < 8; ni++)
            #pragma unroll
            for (int j = 0; j < 4; j++) d[mi][ni][j] = 0.f;

    load_chunk(0, 0);
    cp_commit();

    const int aRow0 = wm * 32 + (lane & 15);
    const int aSel  = lane >> 4;                              // k-half select
    const int bRow0 = wn * 64 + ((lane >> 4) & 1) * 8 + (lane & 7);
    const int bSel  = (lane >> 3) & 1;

    for (int kc = 0; kc < NKC; kc++) {
        if (kc + 1 < NKC) {
            load_chunk((kc + 1) & 1, kc + 1);
            cp_commit();
            cp_wait<1>();
        } else {
            cp_wait<0>();
        }
        __syncthreads();

        uint32_t st = sbase + (kc & 1) * STAGE_BYTES;

        #pragma unroll
        for (int ks = 0; ks < 2; ks++) {
            // A fragments (hi and lo)
            uint32_t aH[2][4], aL[2][4];
            #pragma unroll
            for (int mi = 0; mi < 2; mi++) {
                int row = aRow0 + mi * 16;
                uint32_t c = (uint32_t)((ks * 2 + aSel) ^ ((row >> 1) & 3));
                uint32_t off = row * 64 + c * 16;
                ldm_x4(aH[mi], st + off);
                ldm_x4(aL[mi], st + 8192 + off);
            }
            // B hi fragments
            uint32_t bF[8][2];
            #pragma unroll
            for (int p = 0; p < 4; p++) {
                int row = bRow0 + p * 16;
                uint32_t c = (uint32_t)((ks * 2 + bSel) ^ ((row >> 1) & 3));
                uint32_t r[4];
                ldm_x4(r, st + 16384 + row * 64 + c * 16);
                bF[2*p][0] = r[0]; bF[2*p][1] = r[1];
                bF[2*p+1][0] = r[2]; bF[2*p+1][1] = r[3];
            }
            // hh + lh
            #pragma unroll
            for (int mi = 0; mi < 2; mi++)
                #pragma unroll
                for (int ni = 0; ni < 8; ni++)
                    mma_bf16(d[mi][ni], aH[mi], bF[ni]);
            #pragma unroll
            for (int mi = 0; mi < 2; mi++)
                #pragma unroll
                for (int ni = 0; ni < 8; ni++)
                    mma_bf16(d[mi][ni], aL[mi], bF[ni]);
            // B lo fragments (overwrite bF)
            #pragma unroll
            for (int p = 0; p < 4; p++) {
                int row = bRow0 + p * 16;
                uint32_t c = (uint32_t)((ks * 2 + bSel) ^ ((row >> 1) & 3));
                uint32_t r[4];
                ldm_x4(r, st + 24576 + row * 64 + c * 16);
                bF[2*p][0] = r[0]; bF[2*p][1] = r[1];
                bF[2*p+1][0] = r[2]; bF[2*p+1][1] = r[3];
            }
            // hl
            #pragma unroll
            for (int mi = 0; mi < 2; mi++)
                #pragma unroll
                for (int ni = 0; ni < 8; ni++)
                    mma_bf16(d[mi][ni], aH[mi], bF[ni]);
        }
        __syncthreads();
    }

    // epilogue
    #pragma unroll
    for (int mi = 0; mi < 2; mi++) {
        int r0 = m0 + wm * 32 + mi * 16 + (lane >> 2);
        #pragma unroll
        for (int ni = 0; ni < 8; ni++) {
            int col = n0 + wn * 64 + ni * 8 + (lane & 3) * 2;
            *(float2*)&C[(size_t)r0 * N + col]       = make_float2(d[mi][ni][0], d[mi][ni][1]);
            *(float2*)&C[(size_t)(r0 + 8) * N + col] = make_float2(d[mi][ni][2], d[mi][ni][3]);
        }
    }
}

// ---------------------------------------------------------------------------
// RoPE: in-place on [TOKENS, H, 128] tensor.
// ---------------------------------------------------------------------------
__global__ void rope_kernel(float* __restrict__ t,
                            const float* __restrict__ fc,
                            const float* __restrict__ fs, int H, int total)
{
    int i = blockIdx.x * blockDim.x + threadIdx.x;
    if (i >= total) return;
    int half = i & 63;
    int h    = (i >> 6) % H;
    int tok  = i / (64 * H);
    int s    = tok & (SEQ - 1);
    float c  = fc[s * 64 + half];
    float sn = fs[s * 64 + half];
    float* p = t + (((size_t)tok * H + h) * HD) + 2 * half;
    float a = p[0], b = p[1];
    p[0] = a * c - b * sn;
    p[1] = a * sn + b * c;
}

// ---------------------------------------------------------------------------
// Causal flash attention, fp32, GQA (unchanged — proven)
// ---------------------------------------------------------------------------
__global__ __launch_bounds__(256) void flash_kernel(
    const float* __restrict__ q, const float* __restrict__ k,
    const float* __restrict__ v, float* __restrict__ o)
{
    constexpr int BM = 64, BN = 32, D = HD;
    __shared__ float Ks[BN][D];
    __shared__ float Vs[BN][D];

    const int m0 = blockIdx.x * BM;
    const int h  = blockIdx.y;
    const int b  = blockIdx.z;
    const int kh = h >> 2;
    const int tid = threadIdx.x;
    const int row = tid >> 2;
    const int c4  = tid & 3;
    const int qrow = m0 + row;

    float qreg[32];
    {
        const float* qp = q + (((size_t)b * SEQ + qrow) * NH + h) * D + c4 * 32;
        #pragma unroll
        for (int d = 0; d < 32; d += 4) {
            float4 t = *(const float4*)(qp + d);
            qreg[d] = t.x; qreg[d+1] = t.y; qreg[d+2] = t.z; qreg[d+3] = t.w;
        }
    }

    float acc[32];
    #pragma unroll
    for (int d = 0; d < 32; d++) acc[d] = 0.f;
    float m = -INFINITY, l = 0.f;
    const float scale = 0.08838834764831845f;

    for (int j0 = 0; j0 < m0 + BM; j0 += BN) {
        {
            int base = tid * 16;
            int tr = base >> 7, tc = base & 127;
            const float* kp = k + (((size_t)b * SEQ + j0 + tr) * NKV + kh) * D + tc;
            const float* vp = v + (((size_t)b * SEQ + j0 + tr) * NKV + kh) * D + tc;
            #pragma unroll
            for (int u = 0; u < 16; u += 4) {
                *(float4*)&Ks[tr][tc + u] = *(const float4*)(kp + u);
                *(float4*)&Vs[tr][tc + u] = *(const float4*)(vp + u);
            }
        }
        __syncthreads();

        float s[BN];
        float tile_max = -INFINITY;
        #pragma unroll
        for (int j = 0; j < BN; j++) {
            float p = 0.f;
            const float4* kr = (const float4*)&Ks[j][c4 * 32];
            #pragma unroll
            for (int d4 = 0; d4 < 8; d4++) {
                float4 kv = kr[d4];
                p += qreg[4*d4+0]*kv.x + qreg[4*d4+1]*kv.y
                   + qreg[4*d4+2]*kv.z + qreg[4*d4+3]*kv.w;
            }
            p += __shfl_xor_sync(0xffffffffu, p, 1);
            p += __shfl_xor_sync(0xffffffffu, p, 2);
            p *= scale;
            if (j0 + j > qrow) p = -INFINITY;
            s[j] = p;
            tile_max = fmaxf(tile_max, p);
        }

        float m_new = fmaxf(m, tile_max);
        float corr = __expf(m - m_new);
        l *= corr;
        #pragma unroll
        for (int d = 0; d < 32; d++) acc[d] *= corr;

        #pragma unroll
        for (int j = 0; j < BN; j++) {
            float p = __expf(s[j] - m_new);
            l += p;
            const float4* vr = (const float4*)&Vs[j][c4 * 32];
            #pragma unroll
            for (int d4 = 0; d4 < 8; d4++) {
                float4 vv = vr[d4];
                acc[4*d4+0] += p * vv.x;
                acc[4*d4+1] += p * vv.y;
                acc[4*d4+2] += p * vv.z;
                acc[4*d4+3] += p * vv.w;
            }
        }
        m = m_new;
        __syncthreads();
    }

    float inv = 1.f / l;
    float* op = o + (((size_t)b * SEQ + qrow) * NH + h) * D + c4 * 32;
    #pragma unroll
    for (int d = 0; d < 32; d += 4) {
        float4 t = make_float4(acc[d]*inv, acc[d+1]*inv, acc[d+2]*inv, acc[d+3]*inv);
        *(float4*)(op + d) = t;
    }
}

// ---------------------------------------------------------------------------
extern "C" void kernel_launch(void* const* d_in, const int* in_sizes, int n_in,
                              void* d_out, int out_size)
{
    const float* x  = (const float*)d_in[0];
    const float* wq = (const float*)d_in[1];
    const float* wk = (const float*)d_in[2];
    const float* wv = (const float*)d_in[3];
    const float* wo = (const float*)d_in[4];
    const float* fc = (const float*)d_in[7];
    const float* fs = (const float*)d_in[8];
    float* out = (float*)d_out;

    float *xq, *xk, *xv, *attn;
    __nv_bfloat16 *xhi, *xlo, *athi, *atlo;
    __nv_bfloat16 *wqhi, *wqlo, *wkhi, *wklo, *wvhi, *wvlo, *wohi, *wolo;
    cudaGetSymbolAddress((void**)&xq,   g_xq);
    cudaGetSymbolAddress((void**)&xk,   g_xk);
    cudaGetSymbolAddress((void**)&xv,   g_xv);
    cudaGetSymbolAddress((void**)&attn, g_attn);
    cudaGetSymbolAddress((void**)&xhi,  g_xhi);
    cudaGetSymbolAddress((void**)&xlo,  g_xlo);
    cudaGetSymbolAddress((void**)&athi, g_athi);
    cudaGetSymbolAddress((void**)&atlo, g_atlo);
    cudaGetSymbolAddress((void**)&wqhi, g_wqhi);
    cudaGetSymbolAddress((void**)&wqlo, g_wqlo);
    cudaGetSymbolAddress((void**)&wkhi, g_wkhi);
    cudaGetSymbolAddress((void**)&wklo, g_wklo);
    cudaGetSymbolAddress((void**)&wvhi, g_wvhi);
    cudaGetSymbolAddress((void**)&wvlo, g_wvlo);
    cudaGetSymbolAddress((void**)&wohi, g_wohi);
    cudaGetSymbolAddress((void**)&wolo, g_wolo);

    cudaFuncSetAttribute(hgemm_kernel, cudaFuncAttributeMaxDynamicSharedMemorySize,
                         HG_SMEM);

    // Splits / transposes
    {
        int total = TOKENS * DIM;
        split_act_kernel<<<(total + 255) / 256, 256>>>(x, xhi, xlo, total);
        dim3 blk(32, 8);
        transpose_split_kernel<<<dim3(128, 128), blk>>>(wq, wqhi, wqlo, 4096);
        transpose_split_kernel<<<dim3(128,  32), blk>>>(wk, wkhi, wklo, 1024);
        transpose_split_kernel<<<dim3(128,  32), blk>>>(wv, wvhi, wvlo, 1024);
        transpose_split_kernel<<<dim3(128, 128), blk>>>(wo, wohi, wolo, 4096);
    }

    // QKV projections (fused hi/lo HMMA)
    hgemm_kernel<<<dim3(32, 32), 256, HG_SMEM>>>(xhi, xlo, wqhi, wqlo, xq, 4096);
    hgemm_kernel<<<dim3( 8, 32), 256, HG_SMEM>>>(xhi, xlo, wkhi, wklo, xk, 1024);
    hgemm_kernel<<<dim3( 8, 32), 256, HG_SMEM>>>(xhi, xlo, wvhi, wvlo, xv, 1024);

    // RoPE
    {
        int tq = TOKENS * NH * 64;
        rope_kernel<<<(tq + 255) / 256, 256>>>(xq, fc, fs, NH, tq);
        int tk = TOKENS * NKV * 64;
        rope_kernel<<<(tk + 255) / 256, 256>>>(xk, fc, fs, NKV, tk);
    }

    // Causal flash attention (start_pos = 0, cache zero => keys/values = xk/xv)
    {
        dim3 g(SEQ / 64, NH, BSZ);
        flash_kernel<<<g, 256>>>(xq, xk, xv, attn);
    }

    // Output projection
    {
        int total = TOKENS * DIM;
        split_act_kernel<<<(total + 255) / 256, 256>>>(attn, athi, atlo, total);
        hgemm_kernel<<<dim3(32, 32), 256, HG_SMEM>>>(athi, atlo, wohi, wolo, out, 4096);
    }
}

// round 14
// speedup vs baseline: 1.7831x; 1.1446x over previous
#include <cuda_runtime.h>
#include <cuda_fp16.h>
#include <math.h>
#include <stdint.h>

// Problem constants
#define BSZ 2
#define SEQ 2048
#define DIM 4096
#define NH 32
#define NKV 8
#define HD 128
#define TOKENS (BSZ*SEQ)   // 4096

// ---------------------------------------------------------------------------
// Scratch (device globals — no allocation allowed)
// ---------------------------------------------------------------------------
__device__ float g_xq[(size_t)TOKENS * NH * HD];    // 4096 x 4096
__device__ float g_xk[(size_t)TOKENS * NKV * HD];   // 4096 x 1024
__device__ float g_xv[(size_t)TOKENS * NKV * HD];   // 4096 x 1024
__device__ float g_attn[(size_t)TOKENS * NH * HD];  // 4096 x 4096

__device__ __half g_xh [(size_t)TOKENS * DIM];   // fp16 activations
__device__ __half g_ath[(size_t)TOKENS * DIM];   // fp16 attn output
__device__ __half g_wqh[(size_t)4096 * DIM];     // weights transposed [N,K]
__device__ __half g_wkh[(size_t)1024 * DIM];
__device__ __half g_wvh[(size_t)1024 * DIM];
__device__ __half g_woh[(size_t)4096 * DIM];

// ---------------------------------------------------------------------------
// PTX helpers (sm_80+ portable: cp.async / ldmatrix / mma.sync)
// ---------------------------------------------------------------------------
__device__ __forceinline__ uint32_t smem_u32(const void* p) {
    uint32_t a;
    asm("{ .reg .u64 t; cvta.to.shared.u64 t, %1; cvt.u32.u64 %0, t; }" : "=r"(a) : "l"(p));
    return a;
}
__device__ __forceinline__ void cp16(uint32_t s, const void* g) {
    asm volatile("cp.async.cg.shared.global [%0], [%1], 16;" :: "r"(s), "l"(g) : "memory");
}
__device__ __forceinline__ void cp_commit() {
    asm volatile("cp.async.commit_group;" ::: "memory");
}
template<int N> __device__ __forceinline__ void cp_wait() {
    asm volatile("cp.async.wait_group %0;" :: "n"(N) : "memory");
}
__device__ __forceinline__ void ldm_x4(uint32_t* r, uint32_t addr) {
    asm volatile("ldmatrix.sync.aligned.m8n8.x4.shared.b16 {%0,%1,%2,%3}, [%4];"
                 : "=r"(r[0]), "=r"(r[1]), "=r"(r[2]), "=r"(r[3]) : "r"(addr));
}
__device__ __forceinline__ void mma_f16(float* d, const uint32_t* a, const uint32_t* b) {
    asm volatile(
        "mma.sync.aligned.m16n8k16.row.col.f32.f16.f16.f32 "
        "{%0,%1,%2,%3}, {%4,%5,%6,%7}, {%8,%9}, {%0,%1,%2,%3};"
        : "+f"(d[0]), "+f"(d[1]), "+f"(d[2]), "+f"(d[3])
        : "r"(a[0]), "r"(a[1]), "r"(a[2]), "r"(a[3]), "r"(b[0]), "r"(b[1]));
}

// ---------------------------------------------------------------------------
// Convert kernels
// ---------------------------------------------------------------------------
__global__ void convert_act_kernel(const float* __restrict__ A,
                                   __half* __restrict__ Ah, int total)
{
    int i = blockIdx.x * blockDim.x + threadIdx.x;
    if (i >= total) return;
    Ah[i] = __float2half_rn(A[i]);
}

// Weight transpose+convert: W[4096,N] f32 -> Wh[N,4096] fp16
__global__ void transpose_convert_kernel(const float* __restrict__ W,
                                         __half* __restrict__ Wh, int N)
{
    __shared__ float t[32][33];
    int k0 = blockIdx.x * 32, n0 = blockIdx.y * 32;
    int tx = threadIdx.x, ty = threadIdx.y;   // 32 x 8
    #pragma unroll
    for (int j = 0; j < 4; j++)
        t[ty + j * 8][tx] = W[(size_t)(k0 + ty + j * 8) * N + n0 + tx];
    __syncthreads();
    #pragma unroll
    for (int j = 0; j < 4; j++) {
        int n = n0 + ty + j * 8;
        int k = k0 + tx;
        Wh[(size_t)n * DIM + k] = __float2half_rn(t[tx][ty + j * 8]);
    }
}

// ---------------------------------------------------------------------------
// HMMA GEMM (fp16 in, fp32 out): C[M,N] = A[M,K] . B[N,K]^T,  K=4096.
// BM=BN=128, BK=64, 256 threads (8 warps, warp tile 32x64), 2-stage cp.async.
// Smem row = 64 fp16 = 128B; chunk swizzle c ^ (row&7) -> conflict-free ldmatrix.
// (R6-proven structure; only dtype + K changed.)
// ---------------------------------------------------------------------------
#define HG_SMEM (64 * 1024)
#define NKC (DIM / 64)   // 64

__global__ __launch_bounds__(256) void hgemm_kernel(
    const __half* __restrict__ A,
    const __half* __restrict__ B,
    float* __restrict__ C, int N)
{
    extern __shared__ char smraw[];
    const uint32_t sbase = smem_u32(smraw);   // A0 | B0 | A1 | B1, 16KB each

    const int tid  = threadIdx.x;
    const int lane = tid & 31, warp = tid >> 5;
    const int wm = warp & 3;      // m offset wm*32
    const int wn = warp >> 2;     // n offset wn*64
    const int m0 = blockIdx.y * 128;
    const int n0 = blockIdx.x * 128;

    // loader: each thread owns rows lrow+32i at 16B-chunk lc
    const int lrow = tid >> 3;    // 0..31
    const int lc   = tid & 7;     // 0..7
    const __half* gA = A + (size_t)(m0 + lrow) * DIM + lc * 8;
    const __half* gB = B + (size_t)(n0 + lrow) * DIM + lc * 8;
    uint32_t soff[4];
    #pragma unroll
    for (int i = 0; i < 4; i++) {
        int row = lrow + 32 * i;
        soff[i] = row * 128 + ((lc ^ (row & 7)) * 16);
    }

    auto load_chunk = [&](int buf, int kc) {
        uint32_t sA = sbase + buf * 32768;
        uint32_t sB = sA + 16384;
        size_t koff = (size_t)kc * 64;
        #pragma unroll
        for (int i = 0; i < 4; i++) {
            cp16(sA + soff[i], gA + (size_t)(32 * i) * DIM + koff);
            cp16(sB + soff[i], gB + (size_t)(32 * i) * DIM + koff);
        }
    };

    float d[2][8][4];
    #pragma unroll
    for (int mi = 0; mi < 2; mi++)
        #pragma unroll
        for (int ni = 0; ni < 8; ni++)
            #pragma unroll
            for (int j = 0; j < 4; j++) d[mi][ni][j] = 0.f;

    load_chunk(0, 0);
    cp_commit();

    // precomputed ldmatrix row/col pieces
    const int aRow0 = wm * 32 + (lane & 15);
    const int aSel  = lane >> 4;
    const int bRow0 = wn * 64 + ((lane >> 4) & 1) * 8 + (lane & 7);
    const int bSel  = (lane >> 3) & 1;

    for (int kc = 0; kc < NKC; kc++) {
        if (kc + 1 < NKC) {
            load_chunk((kc + 1) & 1, kc + 1);
            cp_commit();
            cp_wait<1>();
        } else {
            cp_wait<0>();
        }
        __syncthreads();

        uint32_t sA = sbase + (kc & 1) * 32768;
        uint32_t sB = sA + 16384;

        #pragma unroll
        for (int ks = 0; ks < 4; ks++) {
            uint32_t aF[2][4];
            #pragma unroll
            for (int mi = 0; mi < 2; mi++) {
                int row = aRow0 + mi * 16;
                uint32_t c = (uint32_t)((ks * 2 + aSel) ^ (row & 7));
                ldm_x4(aF[mi], sA + row * 128 + c * 16);
            }
            uint32_t bF[8][2];
            #pragma unroll
            for (int p = 0; p < 4; p++) {
                int row = bRow0 + p * 16;
                uint32_t c = (uint32_t)((ks * 2 + bSel) ^ (row & 7));
                uint32_t r[4];
                ldm_x4(r, sB + row * 128 + c * 16);
                bF[2*p][0] = r[0]; bF[2*p][1] = r[1];
                bF[2*p+1][0] = r[2]; bF[2*p+1][1] = r[3];
            }
            #pragma unroll
            for (int mi = 0; mi < 2; mi++)
                #pragma unroll
                for (int ni = 0; ni < 8; ni++)
                    mma_f16(d[mi][ni], aF[mi], bF[ni]);
        }
        __syncthreads();
    }

    // epilogue
    #pragma unroll
    for (int mi = 0; mi < 2; mi++) {
        int r0 = m0 + wm * 32 + mi * 16 + (lane >> 2);
        #pragma unroll
        for (int ni = 0; ni < 8; ni++) {
            int col = n0 + wn * 64 + ni * 8 + (lane & 3) * 2;
            *(float2*)&C[(size_t)r0 * N + col]       = make_float2(d[mi][ni][0], d[mi][ni][1]);
            *(float2*)&C[(size_t)(r0 + 8) * N + col] = make_float2(d[mi][ni][2], d[mi][ni][3]);
        }
    }
}

// ---------------------------------------------------------------------------
// RoPE: in-place on [TOKENS, H, 128] tensor.
// ---------------------------------------------------------------------------
__global__ void rope_kernel(float* __restrict__ t,
                            const float* __restrict__ fc,
                            const float* __restrict__ fs, int H, int total)
{
    int i = blockIdx.x * blockDim.x + threadIdx.x;
    if (i >= total) return;
    int half = i & 63;
    int h    = (i >> 6) % H;
    int tok  = i / (64 * H);
    int s    = tok & (SEQ - 1);
    float c  = fc[s * 64 + half];
    float sn = fs[s * 64 + half];
    float* p = t + (((size_t)tok * H + h) * HD) + 2 * half;
    float a = p[0], b = p[1];
    p[0] = a * c - b * sn;
    p[1] = a * sn + b * c;
}

// ---------------------------------------------------------------------------
// Causal flash attention, fp32, GQA (unchanged — proven)
// ---------------------------------------------------------------------------
__global__ __launch_bounds__(256) void flash_kernel(
    const float* __restrict__ q, const float* __restrict__ k,
    const float* __restrict__ v, float* __restrict__ o)
{
    constexpr int BM = 64, BN = 32, D = HD;
    __shared__ float Ks[BN][D];
    __shared__ float Vs[BN][D];

    const int m0 = blockIdx.x * BM;
    const int h  = blockIdx.y;
    const int b  = blockIdx.z;
    const int kh = h >> 2;
    const int tid = threadIdx.x;
    const int row = tid >> 2;
    const int c4  = tid & 3;
    const int qrow = m0 + row;

    float qreg[32];
    {
        const float* qp = q + (((size_t)b * SEQ + qrow) * NH + h) * D + c4 * 32;
        #pragma unroll
        for (int d = 0; d < 32; d += 4) {
            float4 t = *(const float4*)(qp + d);
            qreg[d] = t.x; qreg[d+1] = t.y; qreg[d+2] = t.z; qreg[d+3] = t.w;
        }
    }

    float acc[32];
    #pragma unroll
    for (int d = 0; d < 32; d++) acc[d] = 0.f;
    float m = -INFINITY, l = 0.f;
    const float scale = 0.08838834764831845f;

    for (int j0 = 0; j0 < m0 + BM; j0 += BN) {
        {
            int base = tid * 16;
            int tr = base >> 7, tc = base & 127;
            const float* kp = k + (((size_t)b * SEQ + j0 + tr) * NKV + kh) * D + tc;
            const float* vp = v + (((size_t)b * SEQ + j0 + tr) * NKV + kh) * D + tc;
            #pragma unroll
            for (int u = 0; u < 16; u += 4) {
                *(float4*)&Ks[tr][tc + u] = *(const float4*)(kp + u);
                *(float4*)&Vs[tr][tc + u] = *(const float4*)(vp + u);
            }
        }
        __syncthreads();

        float s[BN];
        float tile_max = -INFINITY;
        #pragma unroll
        for (int j = 0; j < BN; j++) {
            float p = 0.f;
            const float4* kr = (const float4*)&Ks[j][c4 * 32];
            #pragma unroll
            for (int d4 = 0; d4 < 8; d4++) {
                float4 kv = kr[d4];
                p += qreg[4*d4+0]*kv.x + qreg[4*d4+1]*kv.y
                   + qreg[4*d4+2]*kv.z + qreg[4*d4+3]*kv.w;
            }
            p += __shfl_xor_sync(0xffffffffu, p, 1);
            p += __shfl_xor_sync(0xffffffffu, p, 2);
            p *= scale;
            if (j0 + j > qrow) p = -INFINITY;
            s[j] = p;
            tile_max = fmaxf(tile_max, p);
        }

        float m_new = fmaxf(m, tile_max);
        float corr = __expf(m - m_new);
        l *= corr;
        #pragma unroll
        for (int d = 0; d < 32; d++) acc[d] *= corr;

        #pragma unroll
        for (int j = 0; j < BN; j++) {
            float p = __expf(s[j] - m_new);
            l += p;
            const float4* vr = (const float4*)&Vs[j][c4 * 32];
            #pragma unroll
            for (int d4 = 0; d4 < 8; d4++) {
                float4 vv = vr[d4];
                acc[4*d4+0] += p * vv.x;
                acc[4*d4+1] += p * vv.y;
                acc[4*d4+2] += p * vv.z;
                acc[4*d4+3] += p * vv.w;
            }
        }
        m = m_new;
        __syncthreads();
    }

    float inv = 1.f / l;
    float* op = o + (((size_t)b * SEQ + qrow) * NH + h) * D + c4 * 32;
    #pragma unroll
    for (int d = 0; d < 32; d += 4) {
        float4 t = make_float4(acc[d]*inv, acc[d+1]*inv, acc[d+2]*inv, acc[d+3]*inv);
        *(float4*)(op + d) = t;
    }
}

// ---------------------------------------------------------------------------
extern "C" void kernel_launch(void* const* d_in, const int* in_sizes, int n_in,
                              void* d_out, int out_size)
{
    const float* x  = (const float*)d_in[0];
    const float* wq = (const float*)d_in[1];
    const float* wk = (const float*)d_in[2];
    const float* wv = (const float*)d_in[3];
    const float* wo = (const float*)d_in[4];
    const float* fc = (const float*)d_in[7];
    const float* fs = (const float*)d_in[8];
    float* out = (float*)d_out;

    float *xq, *xk, *xv, *attn;
    __half *xh, *ath, *wqh, *wkh, *wvh, *woh;
    cudaGetSymbolAddress((void**)&xq,   g_xq);
    cudaGetSymbolAddress((void**)&xk,   g_xk);
    cudaGetSymbolAddress((void**)&xv,   g_xv);
    cudaGetSymbolAddress((void**)&attn, g_attn);
    cudaGetSymbolAddress((void**)&xh,   g_xh);
    cudaGetSymbolAddress((void**)&ath,  g_ath);
    cudaGetSymbolAddress((void**)&wqh,  g_wqh);
    cudaGetSymbolAddress((void**)&wkh,  g_wkh);
    cudaGetSymbolAddress((void**)&wvh,  g_wvh);
    cudaGetSymbolAddress((void**)&woh,  g_woh);

    cudaFuncSetAttribute(hgemm_kernel, cudaFuncAttributeMaxDynamicSharedMemorySize,
                         HG_SMEM);

    // Converts / transposes
    {
        int total = TOKENS * DIM;
        convert_act_kernel<<<(total + 255) / 256, 256>>>(x, xh, total);
        dim3 blk(32, 8);
        transpose_convert_kernel<<<dim3(128, 128), blk>>>(wq, wqh, 4096);
        transpose_convert_kernel<<<dim3(128,  32), blk>>>(wk, wkh, 1024);
        transpose_convert_kernel<<<dim3(128,  32), blk>>>(wv, wvh, 1024);
        transpose_convert_kernel<<<dim3(128, 128), blk>>>(wo, woh, 4096);
    }

    // QKV projections (fp16 HMMA, fp32 accumulate)
    hgemm_kernel<<<dim3(32, 32), 256, HG_SMEM>>>(xh, wqh, xq, 4096);
    hgemm_kernel<<<dim3( 8, 32), 256, HG_SMEM>>>(xh, wkh, xk, 1024);
    hgemm_kernel<<<dim3( 8, 32), 256, HG_SMEM>>>(xh, wvh, xv, 1024);

    // RoPE
    {
        int tq = TOKENS * NH * 64;
        rope_kernel<<<(tq + 255) / 256, 256>>>(xq, fc, fs, NH, tq);
        int tk = TOKENS * NKV * 64;
        rope_kernel<<<(tk + 255) / 256, 256>>>(xk, fc, fs, NKV, tk);
    }

    // Causal flash attention (start_pos = 0, cache zero => keys/values = xk/xv)
    {
        dim3 g(SEQ / 64, NH, BSZ);
        flash_kernel<<<g, 256>>>(xq, xk, xv, attn);
    }

    // Output projection
    {
        int total = TOKENS * DIM;
        convert_act_kernel<<<(total + 255) / 256, 256>>>(attn, ath, total);
        hgemm_kernel<<<dim3(32, 32), 256, HG_SMEM>>>(ath, woh, out, 4096);
    }
}

// round 17
// speedup vs baseline: 21.2923x; 11.9412x over previous
#include <cuda_runtime.h>
#include <cuda_fp16.h>
#include <math.h>
#include <stdint.h>

// Problem constants
#define BSZ 2
#define SEQ 2048
#define DIM 4096
#define NH 32
#define NKV 8
#define HD 128
#define TOKENS (BSZ*SEQ)   // 4096

// ---------------------------------------------------------------------------
// Scratch (device globals — no allocation allowed)
// ---------------------------------------------------------------------------
__device__ float g_xq[(size_t)TOKENS * NH * HD];    // fp32 Q proj
__device__ float g_xk[(size_t)TOKENS * NKV * HD];   // fp32 K proj
__device__ float g_xv[(size_t)TOKENS * NKV * HD];   // fp32 V proj

__device__ __half g_xh [(size_t)TOKENS * DIM];      // fp16 activations
__device__ __half g_ath[(size_t)TOKENS * DIM];      // fp16 attn output (flash writes)
__device__ __half g_qh [(size_t)TOKENS * NH * HD];  // fp16 roped Q (prescaled)
__device__ __half g_kh [(size_t)TOKENS * NKV * HD]; // fp16 roped K
__device__ __half g_vt [(size_t)BSZ * NKV * HD * SEQ]; // fp16 V transposed [b][kh][d][s]
__device__ __half g_wqh[(size_t)4096 * DIM];        // weights transposed [N,K]
__device__ __half g_wkh[(size_t)1024 * DIM];
__device__ __half g_wvh[(size_t)1024 * DIM];
__device__ __half g_woh[(size_t)4096 * DIM];

// ---------------------------------------------------------------------------
// PTX helpers (sm_80+ portable: cp.async / ldmatrix / mma.sync)
// ---------------------------------------------------------------------------
__device__ __forceinline__ uint32_t smem_u32(const void* p) {
    uint32_t a;
    asm("{ .reg .u64 t; cvta.to.shared.u64 t, %1; cvt.u32.u64 %0, t; }" : "=r"(a) : "l"(p));
    return a;
}
__device__ __forceinline__ void cp16(uint32_t s, const void* g) {
    asm volatile("cp.async.cg.shared.global [%0], [%1], 16;" :: "r"(s), "l"(g) : "memory");
}
__device__ __forceinline__ void cp_commit() {
    asm volatile("cp.async.commit_group;" ::: "memory");
}
template<int N> __device__ __forceinline__ void cp_wait() {
    asm volatile("cp.async.wait_group %0;" :: "n"(N) : "memory");
}
__device__ __forceinline__ void ldm_x4(uint32_t* r, uint32_t addr) {
    asm volatile("ldmatrix.sync.aligned.m8n8.x4.shared.b16 {%0,%1,%2,%3}, [%4];"
                 : "=r"(r[0]), "=r"(r[1]), "=r"(r[2]), "=r"(r[3]) : "r"(addr));
}
__device__ __forceinline__ void mma_f16(float* d, const uint32_t* a, const uint32_t* b) {
    asm volatile(
        "mma.sync.aligned.m16n8k16.row.col.f32.f16.f16.f32 "
        "{%0,%1,%2,%3}, {%4,%5,%6,%7}, {%8,%9}, {%0,%1,%2,%3};"
        : "+f"(d[0]), "+f"(d[1]), "+f"(d[2]), "+f"(d[3])
        : "r"(a[0]), "r"(a[1]), "r"(a[2]), "r"(a[3]), "r"(b[0]), "r"(b[1]));
}
__device__ __forceinline__ uint32_t h2u(__half2 v) {
    return *reinterpret_cast<uint32_t*>(&v);
}

// ---------------------------------------------------------------------------
// Convert kernels
// ---------------------------------------------------------------------------
__global__ void convert_act_kernel(const float* __restrict__ A,
                                   __half* __restrict__ Ah, int total)
{
    int i = blockIdx.x * blockDim.x + threadIdx.x;
    if (i >= total) return;
    Ah[i] = __float2half_rn(A[i]);
}

// Weight transpose+convert: W[4096,N] f32 -> Wh[N,4096] fp16
__global__ void transpose_convert_kernel(const float* __restrict__ W,
                                         __half* __restrict__ Wh, int N)
{
    __shared__ float t[32][33];
    int k0 = blockIdx.x * 32, n0 = blockIdx.y * 32;
    int tx = threadIdx.x, ty = threadIdx.y;   // 32 x 8
    #pragma unroll
    for (int j = 0; j < 4; j++)
        t[ty + j * 8][tx] = W[(size_t)(k0 + ty + j * 8) * N + n0 + tx];
    __syncthreads();
    #pragma unroll
    for (int j = 0; j < 4; j++) {
        int n = n0 + ty + j * 8;
        int k = k0 + tx;
        Wh[(size_t)n * DIM + k] = __float2half_rn(t[tx][ty + j * 8]);
    }
}

// RoPE + fp16 convert: reads fp32 [tok,H,128], writes fp16 same layout.
__global__ void rope_convert_kernel(const float* __restrict__ t,
                                    __half* __restrict__ out,
                                    const float* __restrict__ fc,
                                    const float* __restrict__ fs,
                                    int H, float scale, int total)
{
    int i = blockIdx.x * blockDim.x + threadIdx.x;
    if (i >= total) return;
    int half = i & 63;
    int h    = (i >> 6) % H;
    int tok  = i / (64 * H);
    int s    = tok & (SEQ - 1);
    float c  = fc[s * 64 + half];
    float sn = fs[s * 64 + half];
    size_t base = (((size_t)tok * H + h) * HD) + 2 * half;
    float a = t[base], b = t[base + 1];
    *(__half2*)(out + base) = __floats2half2_rn((a * c - b * sn) * scale,
                                                (a * sn + b * c) * scale);
}

// V transpose+convert: xv fp32 [b,s,kh,d] -> vt fp16 [b][kh][d][s]
__global__ void convert_vt_kernel(const float* __restrict__ xv,
                                  __half* __restrict__ vt)
{
    __shared__ float t[32][33];
    int s0 = blockIdx.x * 32, d0 = blockIdx.y * 32;
    int bz = blockIdx.z;
    int b = bz / NKV, kh = bz % NKV;
    int tx = threadIdx.x, ty = threadIdx.y;   // 32 x 8
    #pragma unroll
    for (int j = 0; j < 4; j++) {
        int s = s0 + ty + j * 8;
        t[ty + j * 8][tx] = xv[((size_t)(b * SEQ + s) * NKV + kh) * HD + d0 + tx];
    }
    __syncthreads();
    #pragma unroll
    for (int j = 0; j < 4; j++) {
        int d = d0 + ty + j * 8;
        int s = s0 + tx;
        vt[((size_t)(b * NKV + kh) * HD + d) * SEQ + s] = __float2half_rn(t[tx][ty + j * 8]);
    }
}

// ---------------------------------------------------------------------------
// HMMA GEMM (fp16 in, fp32 out): C[M,N] = A[M,K] . B[N,K]^T,  K=4096.
// (R14-proven, unchanged.)
// ---------------------------------------------------------------------------
#define HG_SMEM (64 * 1024)
#define NKC (DIM / 64)   // 64

__global__ __launch_bounds__(256) void hgemm_kernel(
    const __half* __restrict__ A,
    const __half* __restrict__ B,
    float* __restrict__ C, int N)
{
    extern __shared__ char smraw[];
    const uint32_t sbase = smem_u32(smraw);

    const int tid  = threadIdx.x;
    const int lane = tid & 31, warp = tid >> 5;
    const int wm = warp & 3;
    const int wn = warp >> 2;
    const int m0 = blockIdx.y * 128;
    const int n0 = blockIdx.x * 128;

    const int lrow = tid >> 3;
    const int lc   = tid & 7;
    const __half* gA = A + (size_t)(m0 + lrow) * DIM + lc * 8;
    const __half* gB = B + (size_t)(n0 + lrow) * DIM + lc * 8;
    uint32_t soff[4];
    #pragma unroll
    for (int i = 0; i < 4; i++) {
        int row = lrow + 32 * i;
        soff[i] = row * 128 + ((lc ^ (row & 7)) * 16);
    }

    auto load_chunk = [&](int buf, int kc) {
        uint32_t sA = sbase + buf * 32768;
        uint32_t sB = sA + 16384;
        size_t koff = (size_t)kc * 64;
        #pragma unroll
        for (int i = 0; i < 4; i++) {
            cp16(sA + soff[i], gA + (size_t)(32 * i) * DIM + koff);
            cp16(sB + soff[i], gB + (size_t)(32 * i) * DIM + koff);
        }
    };

    float d[2][8][4];
    #pragma unroll
    for (int mi = 0; mi < 2; mi++)
        #pragma unroll
        for (int ni = 0; ni < 8; ni++)
            #pragma unroll
            for (int j = 0; j < 4; j++) d[mi][ni][j] = 0.f;

    load_chunk(0, 0);
    cp_commit();

    const int aRow0 = wm * 32 + (lane & 15);
    const int aSel  = lane >> 4;
    const int bRow0 = wn * 64 + ((lane >> 4) & 1) * 8 + (lane & 7);
    const int bSel  = (lane >> 3) & 1;

    for (int kc = 0; kc < NKC; kc++) {
        if (kc + 1 < NKC) {
            load_chunk((kc + 1) & 1, kc + 1);
            cp_commit();
            cp_wait<1>();
        } else {
            cp_wait<0>();
        }
        __syncthreads();

        uint32_t sA = sbase + (kc & 1) * 32768;
        uint32_t sB = sA + 16384;

        #pragma unroll
        for (int ks = 0; ks < 4; ks++) {
            uint32_t aF[2][4];
            #pragma unroll
            for (int mi = 0; mi < 2; mi++) {
                int row = aRow0 + mi * 16;
                uint32_t c = (uint32_t)((ks * 2 + aSel) ^ (row & 7));
                ldm_x4(aF[mi], sA + row * 128 + c * 16);
            }
            uint32_t bF[8][2];
            #pragma unroll
            for (int p = 0; p < 4; p++) {
                int row = bRow0 + p * 16;
                uint32_t c = (uint32_t)((ks * 2 + bSel) ^ (row & 7));
                uint32_t r[4];
                ldm_x4(r, sB + row * 128 + c * 16);
                bF[2*p][0] = r[0]; bF[2*p][1] = r[1];
                bF[2*p+1][0] = r[2]; bF[2*p+1][1] = r[3];
            }
            #pragma unroll
            for (int mi = 0; mi < 2; mi++)
                #pragma unroll
                for (int ni = 0; ni < 8; ni++)
                    mma_f16(d[mi][ni], aF[mi], bF[ni]);
        }
        __syncthreads();
    }

    #pragma unroll
    for (int mi = 0; mi < 2; mi++) {
        int r0 = m0 + wm * 32 + mi * 16 + (lane >> 2);
        #pragma unroll
        for (int ni = 0; ni < 8; ni++) {
            int col = n0 + wn * 64 + ni * 8 + (lane & 3) * 2;
            *(float2*)&C[(size_t)r0 * N + col]       = make_float2(d[mi][ni][0], d[mi][ni][1]);
            *(float2*)&C[(size_t)(r0 + 8) * N + col] = make_float2(d[mi][ni][2], d[mi][ni][3]);
        }
    }
}

// ---------------------------------------------------------------------------
// Tensor-core flash attention (fp16 mma, fp32 accum, online softmax).
// grid (SEQ/64, NH, BSZ), 128 threads (4 warps, warp = 16 q-rows).
// ---------------------------------------------------------------------------
#define FL_SMEM (48 * 1024 + 1024)

__global__ __launch_bounds__(128) void flash_kernel(
    const __half* __restrict__ qh, const __half* __restrict__ kh,
    const __half* __restrict__ vt, __half* __restrict__ o)
{
    extern __shared__ char sm[];
    const uint32_t QS = (smem_u32(sm) + 255) & ~255u;
    const uint32_t KS = QS + 16384;
    const uint32_t VS = KS + 16384;

    const int tid = threadIdx.x, lane = tid & 31, warp = tid >> 5;
    const int m0 = blockIdx.x * 64;
    const int h  = blockIdx.y;
    const int b  = blockIdx.z;
    const int kvh = h >> 2;

    // ---- load Q tile (64 rows x 256B, swizzled) ----
    {
        int lr = tid >> 1;
        int c0 = (tid & 1) * 8;
        const __half* gq = qh + ((size_t)(b * SEQ + m0 + lr) * NH + h) * HD;
        #pragma unroll
        for (int c = 0; c < 8; c++) {
            int cc = c0 + c;
            cp16(QS + lr * 256 + ((cc ^ (lr & 7)) * 16), gq + cc * 8);
        }
    }
    cp_commit();
    cp_wait<0>();
    __syncthreads();

    // ---- persistent Q A-fragments (8 k-steps over d=128) ----
    uint32_t qa[8][4];
    {
        int row = warp * 16 + (lane & 15);
        int sel = lane >> 4;
        #pragma unroll
        for (int ks = 0; ks < 8; ks++) {
            uint32_t c = (uint32_t)((ks * 2 + sel) ^ (row & 7));
            ldm_x4(qa[ks], QS + row * 256 + c * 16);
        }
    }

    const int klr = tid >> 1;
    const int kc0 = (tid & 1) * 8;
    const __half* gk = kh + ((size_t)(b * SEQ + klr) * NKV + kvh) * HD;
    uint32_t kso[8];
    #pragma unroll
    for (int c = 0; c < 8; c++)
        kso[c] = klr * 256 + (((kc0 + c) ^ (klr & 7)) * 16);
    const __half* gv = vt + ((size_t)(b * NKV + kvh) * HD + tid) * SEQ;
    uint32_t vso[8];
    #pragma unroll
    for (int c = 0; c < 8; c++)
        vso[c] = tid * 128 + ((c ^ (tid & 7)) * 16);

    float oacc[16][4];
    #pragma unroll
    for (int i = 0; i < 16; i++)
        #pragma unroll
        for (int j = 0; j < 4; j++) oacc[i][j] = 0.f;
    float mrow0 = -1e30f, mrow1 = -1e30f, lrow0 = 0.f, lrow1 = 0.f;

    const int rr  = lane >> 2;
    const int cc2 = (lane & 3) * 2;

    for (int j0 = 0; j0 <= m0; j0 += 64) {
        #pragma unroll
        for (int c = 0; c < 8; c++)
            cp16(KS + kso[c], gk + (size_t)j0 * NKV * HD + (kc0 + c) * 8);
        #pragma unroll
        for (int c = 0; c < 8; c++)
            cp16(VS + vso[c], gv + j0 + c * 8);
        cp_commit();
        cp_wait<0>();
        __syncthreads();

        // ---- S = Q K^T (16 x 64 per warp) ----
        float s[8][4];
        #pragma unroll
        for (int i = 0; i < 8; i++)
            #pragma unroll
            for (int j = 0; j < 4; j++) s[i][j] = 0.f;

        #pragma unroll
        for (int ks = 0; ks < 8; ks++) {
            #pragma unroll
            for (int np = 0; np < 4; np++) {
                int row = np * 16 + ((lane >> 4) & 1) * 8 + (lane & 7);
                uint32_t c = (uint32_t)((ks * 2 + ((lane >> 3) & 1)) ^ (row & 7));
                uint32_t r4[4];
                ldm_x4(r4, KS + row * 256 + c * 16);
                mma_f16(s[2 * np],     qa[ks], r4);
                mma_f16(s[2 * np + 1], qa[ks], r4 + 2);
            }
        }

        // ---- causal mask (diagonal tile only) ----
        if (j0 == m0) {
            int q0 = warp * 16 + rr;
            #pragma unroll
            for (int nf = 0; nf < 8; nf++) {
                int col = nf * 8 + cc2;
                if (col     > q0)     s[nf][0] = -1e30f;
                if (col + 1 > q0)     s[nf][1] = -1e30f;
                if (col     > q0 + 8) s[nf][2] = -1e30f;
                if (col + 1 > q0 + 8) s[nf][3] = -1e30f;
            }
        }

        // ---- online softmax ----
        float tm0 = -1e30f, tm1 = -1e30f;
        #pragma unroll
        for (int nf = 0; nf < 8; nf++) {
            tm0 = fmaxf(tm0, fmaxf(s[nf][0], s[nf][1]));
            tm1 = fmaxf(tm1, fmaxf(s[nf][2], s[nf][3]));
        }
        tm0 = fmaxf(tm0, __shfl_xor_sync(0xffffffffu, tm0, 1));
        tm0 = fmaxf(tm0, __shfl_xor_sync(0xffffffffu, tm0, 2));
        tm1 = fmaxf(tm1, __shfl_xor_sync(0xffffffffu, tm1, 1));
        tm1 = fmaxf(tm1, __shfl_xor_sync(0xffffffffu, tm1, 2));

        float mn0 = fmaxf(mrow0, tm0), mn1 = fmaxf(mrow1, tm1);
        float corr0 = __expf(mrow0 - mn0), corr1 = __expf(mrow1 - mn1);
        mrow0 = mn0; mrow1 = mn1;

        float ls0 = 0.f, ls1 = 0.f;
        #pragma unroll
        for (int nf = 0; nf < 8; nf++) {
            s[nf][0] = __expf(s[nf][0] - mn0);
            s[nf][1] = __expf(s[nf][1] - mn0);
            s[nf][2] = __expf(s[nf][2] - mn1);
            s[nf][3] = __expf(s[nf][3] - mn1);
            ls0 += s[nf][0] + s[nf][1];
            ls1 += s[nf][2] + s[nf][3];
        }
        ls0 += __shfl_xor_sync(0xffffffffu, ls0, 1);
        ls0 += __shfl_xor_sync(0xffffffffu, ls0, 2);
        ls1 += __shfl_xor_sync(0xffffffffu, ls1, 1);
        ls1 += __shfl_xor_sync(0xffffffffu, ls1, 2);
        lrow0 = lrow0 * corr0 + ls0;
        lrow1 = lrow1 * corr1 + ls1;

        #pragma unroll
        for (int i = 0; i < 16; i++) {
            oacc[i][0] *= corr0; oacc[i][1] *= corr0;
            oacc[i][2] *= corr1; oacc[i][3] *= corr1;
        }

        // ---- P fp16 A-fragments (layout-exact repack) ----
        uint32_t pa[4][4];
        #pragma unroll
        for (int kp = 0; kp < 4; kp++) {
            pa[kp][0] = h2u(__floats2half2_rn(s[2*kp][0],   s[2*kp][1]));
            pa[kp][1] = h2u(__floats2half2_rn(s[2*kp][2],   s[2*kp][3]));
            pa[kp][2] = h2u(__floats2half2_rn(s[2*kp+1][0], s[2*kp+1][1]));
            pa[kp][3] = h2u(__floats2half2_rn(s[2*kp+1][2], s[2*kp+1][3]));
        }

        // ---- O += P V (Vt rows = d, proven non-trans B path) ----
        #pragma unroll
        for (int kp = 0; kp < 4; kp++) {
            #pragma unroll
            for (int np = 0; np < 8; np++) {
                int row = np * 16 + ((lane >> 4) & 1) * 8 + (lane & 7);
                uint32_t c = (uint32_t)((kp * 2 + ((lane >> 3) & 1)) ^ (row & 7));
                uint32_t r4[4];
                ldm_x4(r4, VS + row * 128 + c * 16);
                mma_f16(oacc[2 * np],     pa[kp], r4);
                mma_f16(oacc[2 * np + 1], pa[kp], r4 + 2);
            }
        }
        __syncthreads();
    }

    // ---- epilogue ----
    float inv0 = 1.f / lrow0, inv1 = 1.f / lrow1;
    int r0 = m0 + warp * 16 + rr;
    #pragma unroll
    for (int nf = 0; nf < 16; nf++) {
        int col = nf * 8 + cc2;
        size_t base0 = ((size_t)(b * SEQ + r0) * NH + h) * HD + col;
        size_t base1 = ((size_t)(b * SEQ + r0 + 8) * NH + h) * HD + col;
        *(__half2*)(o + base0) = __floats2half2_rn(oacc[nf][0] * inv0, oacc[nf][1] * inv0);
        *(__half2*)(o + base1) = __floats2half2_rn(oacc[nf][2] * inv1, oacc[nf][3] * inv1);
    }
}

// ---------------------------------------------------------------------------
extern "C" void kernel_launch(void* const* d_in, const int* in_sizes, int n_in,
                              void* d_out, int out_size)
{
    const float* x  = (const float*)d_in[0];
    const float* wq = (const float*)d_in[1];
    const float* wk = (const float*)d_in[2];
    const float* wv = (const float*)d_in[3];
    const float* wo = (const float*)d_in[4];
    const float* fc = (const float*)d_in[7];
    const float* fs = (const float*)d_in[8];
    float* out = (float*)d_out;

    float *xq, *xk, *xv;
    __half *xh, *ath, *qh, *kh, *vt, *wqh, *wkh, *wvh, *woh;
    cudaGetSymbolAddress((void**)&xq,  g_xq);
    cudaGetSymbolAddress((void**)&xk,  g_xk);
    cudaGetSymbolAddress((void**)&xv,  g_xv);
    cudaGetSymbolAddress((void**)&xh,  g_xh);
    cudaGetSymbolAddress((void**)&ath, g_ath);
    cudaGetSymbolAddress((void**)&qh,  g_qh);
    cudaGetSymbolAddress((void**)&kh,  g_kh);
    cudaGetSymbolAddress((void**)&vt,  g_vt);
    cudaGetSymbolAddress((void**)&wqh, g_wqh);
    cudaGetSymbolAddress((void**)&wkh, g_wkh);
    cudaGetSymbolAddress((void**)&wvh, g_wvh);
    cudaGetSymbolAddress((void**)&woh, g_woh);

    cudaFuncSetAttribute(hgemm_kernel, cudaFuncAttributeMaxDynamicSharedMemorySize,
                         HG_SMEM);
    cudaFuncSetAttribute(flash_kernel, cudaFuncAttributeMaxDynamicSharedMemorySize,
                         FL_SMEM);

    // Converts / transposes
    {
        int total = TOKENS * DIM;
        convert_act_kernel<<<(total + 255) / 256, 256>>>(x, xh, total);
        dim3 blk(32, 8);
        transpose_convert_kernel<<<dim3(128, 128), blk>>>(wq, wqh, 4096);
        transpose_convert_kernel<<<dim3(128,  32), blk>>>(wk, wkh, 1024);
        transpose_convert_kernel<<<dim3(128,  32), blk>>>(wv, wvh, 1024);
        transpose_convert_kernel<<<dim3(128, 128), blk>>>(wo, woh, 4096);
    }

    // QKV projections (fp16 HMMA, fp32 accumulate)
    hgemm_kernel<<<dim3(32, 32), 256, HG_SMEM>>>(xh, wqh, xq, 4096);
    hgemm_kernel<<<dim3( 8, 32), 256, HG_SMEM>>>(xh, wkh, xk, 1024);
    hgemm_kernel<<<dim3( 8, 32), 256, HG_SMEM>>>(xh, wvh, xv, 1024);

    // RoPE + fp16 converts (Q prescaled by 1/sqrt(HD)); V transpose-convert
    {
        int tq = TOKENS * NH * 64;
        rope_convert_kernel<<<(tq + 255) / 256, 256>>>(xq, qh, fc, fs, NH,
                                                       0.08838834764831845f, tq);
        int tk = TOKENS * NKV * 64;
        rope_convert_kernel<<<(tk + 255) / 256, 256>>>(xk, kh, fc, fs, NKV, 1.0f, tk);
        dim3 blk(32, 8);
        convert_vt_kernel<<<dim3(SEQ / 32, HD / 32, BSZ * NKV), blk>>>(xv, vt);
    }

    // Tensor-core flash attention -> fp16 ath
    {
        dim3 g(SEQ / 64, NH, BSZ);
        flash_kernel<<<g, 128, FL_SMEM>>>(qh, kh, vt, ath);
    }

    // Output projection
    hgemm_kernel<<<dim3(32, 32), 256, HG_SMEM>>>(ath, woh, out, 4096);
}